// round 5
// baseline (speedup 1.0000x reference)
#include <cuda_runtime.h>
#include <math.h>
#include <stdint.h>

// Problem constants
#define NN_    16
#define CC_    192
#define TT_    120
#define VV_    100
#define HEADS_ 4
#define HCH_   48
#define TV_    (TT_*VV_)      // 12000

#define SPLITK2 5
#define KCHUNK2 1152          // 5760 / 5, multiple of 32

// Scratch (device globals: allocation-free rule)
__device__ float g_q[NN_*CC_*TV_];                        // 147.5 MB
__device__ float g_k[NN_*CC_*TV_];                        // 147.5 MB
__device__ float g_attn[NN_*HEADS_*VV_*VV_];              // 2.56 MB
__device__ float g_part[NN_*HEADS_*SPLITK2*VV_*VV_];      // 12.8 MB
__device__ float g_vals[NN_*HEADS_*CC_*TV_];              // 590 MB

// ---------------------------------------------------------------------------
// helpers
// ---------------------------------------------------------------------------
__device__ __forceinline__ void cp16(float* s, const float* g, bool ok) {
    uint32_t sa = (uint32_t)__cvta_generic_to_shared(s);
    int sz = ok ? 16 : 0;
    asm volatile("cp.async.cg.shared.global [%0], [%1], 16, %2;\n"
                 :: "r"(sa), "l"(g), "r"(sz));
}

// Split v0,v1 (k and k+1) into packed bf16 hi and lo fragments.
// reg layout: low 16 bits = element k (v0), high 16 bits = element k+1 (v1).
__device__ __forceinline__ void cvt_hilo(float v0, float v1, uint32_t& h, uint32_t& l) {
    asm("cvt.rn.bf16x2.f32 %0, %1, %2;" : "=r"(h) : "f"(v1), "f"(v0));
    float h0 = __uint_as_float(h << 16);
    float h1 = __uint_as_float(h & 0xffff0000u);
    asm("cvt.rn.bf16x2.f32 %0, %1, %2;" : "=r"(l) : "f"(v1 - h1), "f"(v0 - h0));
}

__device__ __forceinline__ void mma_bf16(float* c, const uint32_t* a, const uint32_t* b) {
    asm volatile(
        "mma.sync.aligned.m16n8k16.row.col.f32.bf16.bf16.f32 "
        "{%0,%1,%2,%3}, {%4,%5,%6,%7}, {%8,%9}, {%0,%1,%2,%3};\n"
        : "+f"(c[0]), "+f"(c[1]), "+f"(c[2]), "+f"(c[3])
        : "r"(a[0]), "r"(a[1]), "r"(a[2]), "r"(a[3]), "r"(b[0]), "r"(b[1]));
}

// ---------------------------------------------------------------------------
// bf16x3 emulated-fp32 GEMM.
//   C[m,n] = sum_k A(m,k) * B(k,n)
//   AKM=false : A[m*lda + k]   (row k-contiguous)
//   AKM=true  : A[k*lda + m]   (k-major, used by the attention-score GEMM)
//   B always B[k*ldb + n]
// Tiles: 128x128x32, 512 threads = 16 warps (4x4), warp tile 32x32.
// EPI: 0 = plain store, 1 = +bias[m], 3 = raw partial store (split-K)
// ---------------------------------------------------------------------------
template<int EPI, bool AKM>
__global__ __launch_bounds__(512)
void mma_gemm(const float* __restrict__ A, const float* __restrict__ B,
              float* __restrict__ C,
              int M, int N, int K, int lda, int ldb, int ldc,
              long aO, long aI, long bO, long bI, long cO, long cI,
              int innerCnt, int splitK, int kChunk,
              const float* __restrict__ bias)
{
    extern __shared__ float smem[];
    constexpr int AROW = 40;                 // padded row (32 k + 8 pad) for AKM=false
    constexpr int KROW = 132;                // padded row (128 + 4) for k-major tiles
    constexpr int ASZ  = AKM ? 32*KROW : 128*AROW;
    constexpr int BSZ  = 32*KROW;
    constexpr int STG  = ASZ + BSZ;

    const int bz    = blockIdx.z;
    const int b     = bz / splitK;
    const int sk    = bz - b*splitK;
    const int outer = b / innerCnt;
    const int inner = b - outer*innerCnt;
    A += outer*aO + inner*aI;
    B += outer*bO + inner*bI;
    if (EPI == 3) C += (size_t)bz * ((size_t)M * (size_t)N);
    else          C += outer*cO + inner*cI;

    const int kbeg = sk * kChunk;
    const int kend = min(K, kbeg + kChunk);

    const int tid    = threadIdx.x;
    const int wid    = tid >> 5;
    const int lane   = tid & 31;
    const int grp    = lane >> 2;    // 0..7
    const int thr    = lane & 3;     // 0..3
    const int warpM  = (wid >> 2) * 32;
    const int warpN  = (wid & 3) * 32;
    const int blockM = blockIdx.y * 128;
    const int blockN = blockIdx.x * 128;

    float acc[2][4][4];
#pragma unroll
    for (int i = 0; i < 2; i++)
#pragma unroll
        for (int j = 0; j < 4; j++)
#pragma unroll
            for (int l = 0; l < 4; l++) acc[i][j][l] = 0.f;

    // ---- async copy of one k-chunk into stage ----
    auto copy_chunk = [&](int k0, int stage) {
        float* As = smem + stage*STG;
        float* Bs = As + ASZ;
        if (AKM) {
#pragma unroll
            for (int e = 0; e < 2; e++) {
                int kr = (tid >> 5) + e*16;
                int g  = tid & 31;
                bool ok = (k0 + kr < kend) && (blockM + g*4 < M);
                cp16(As + kr*KROW + g*4,
                     A + (size_t)(k0 + kr)*lda + blockM + g*4, ok);
            }
        } else {
#pragma unroll
            for (int e = 0; e < 2; e++) {
                int m = (tid >> 3) + e*64;
                int g = tid & 7;
                bool ok = (blockM + m < M) && (k0 + g*4 < kend);
                cp16(As + m*AROW + g*4,
                     A + (size_t)(blockM + m)*lda + k0 + g*4, ok);
            }
        }
#pragma unroll
        for (int e = 0; e < 2; e++) {
            int kr = (tid >> 5) + e*16;
            int g  = tid & 31;
            bool ok = (k0 + kr < kend) && (blockN + g*4 < N);
            cp16(Bs + kr*KROW + g*4,
                 B + (size_t)(k0 + kr)*ldb + blockN + g*4, ok);
        }
        asm volatile("cp.async.commit_group;\n" ::: "memory");
    };

    // ---- compute one k-chunk (two k16 steps), 3 MMAs per tile (bf16x3) ----
    auto compute_chunk = [&](int stage) {
        const float* As = smem + stage*STG;
        const float* Bs = As + ASZ;
#pragma unroll
        for (int ks = 0; ks < 2; ks++) {
            const int kof = ks * 16;
            uint32_t ah[2][4], al[2][4], bh[4][2], bl[4][2];
#pragma unroll
            for (int mt = 0; mt < 2; mt++) {
                const int m0 = warpM + mt*16 + grp;
                if (!AKM) {
                    float2 v00 = *(const float2*)(As + (size_t)m0*AROW     + kof + thr*2);
                    float2 v10 = *(const float2*)(As + (size_t)(m0+8)*AROW + kof + thr*2);
                    float2 v01 = *(const float2*)(As + (size_t)m0*AROW     + kof + thr*2 + 8);
                    float2 v11 = *(const float2*)(As + (size_t)(m0+8)*AROW + kof + thr*2 + 8);
                    cvt_hilo(v00.x, v00.y, ah[mt][0], al[mt][0]);
                    cvt_hilo(v10.x, v10.y, ah[mt][1], al[mt][1]);
                    cvt_hilo(v01.x, v01.y, ah[mt][2], al[mt][2]);
                    cvt_hilo(v11.x, v11.y, ah[mt][3], al[mt][3]);
                } else {
                    const int k0 = kof + thr*2;
                    cvt_hilo(As[(k0  )*KROW + m0  ], As[(k0+1)*KROW + m0  ], ah[mt][0], al[mt][0]);
                    cvt_hilo(As[(k0  )*KROW + m0+8], As[(k0+1)*KROW + m0+8], ah[mt][1], al[mt][1]);
                    cvt_hilo(As[(k0+8)*KROW + m0  ], As[(k0+9)*KROW + m0  ], ah[mt][2], al[mt][2]);
                    cvt_hilo(As[(k0+8)*KROW + m0+8], As[(k0+9)*KROW + m0+8], ah[mt][3], al[mt][3]);
                }
            }
#pragma unroll
            for (int nt = 0; nt < 4; nt++) {
                const int n0 = warpN + nt*8 + grp;
                const int k0 = kof + thr*2;
                cvt_hilo(Bs[(k0  )*KROW + n0], Bs[(k0+1)*KROW + n0], bh[nt][0], bl[nt][0]);
                cvt_hilo(Bs[(k0+8)*KROW + n0], Bs[(k0+9)*KROW + n0], bh[nt][1], bl[nt][1]);
            }
#pragma unroll
            for (int mt = 0; mt < 2; mt++)
#pragma unroll
                for (int nt = 0; nt < 4; nt++) {
                    mma_bf16(acc[mt][nt], ah[mt], bh[nt]);
                    mma_bf16(acc[mt][nt], al[mt], bh[nt]);
                    mma_bf16(acc[mt][nt], ah[mt], bl[nt]);
                }
        }
    };

    const int nk = (kend - kbeg + 31) / 32;
    copy_chunk(kbeg, 0);
    for (int kt = 0; kt < nk; kt++) {
        if (kt + 1 < nk) {
            copy_chunk(kbeg + (kt+1)*32, (kt+1) & 1);
            asm volatile("cp.async.wait_group 1;\n" ::: "memory");
        } else {
            asm volatile("cp.async.wait_group 0;\n" ::: "memory");
        }
        __syncthreads();
        compute_chunk(kt & 1);
        __syncthreads();
    }

    // ---- epilogue ----
#pragma unroll
    for (int mt = 0; mt < 2; mt++) {
        const int mrow0 = blockM + warpM + mt*16 + grp;
#pragma unroll
        for (int half = 0; half < 2; half++) {
            const int m = mrow0 + half*8;
            if (m >= M) continue;
            float badd = 0.f;
            if (EPI == 1) badd = bias[m];
#pragma unroll
            for (int nt = 0; nt < 4; nt++) {
                const int n = blockN + warpN + nt*8 + thr*2;
                if (n >= N) continue;
                float v0 = acc[mt][nt][half*2 + 0] + badd;
                float v1 = acc[mt][nt][half*2 + 1] + badd;
                *(float2*)(C + (size_t)m*ldc + n) = make_float2(v0, v1);
            }
        }
    }
}

// ---------------------------------------------------------------------------
// split-K combine + attention epilogue: tanh(sum/5760)*alpha + global_attn
// ---------------------------------------------------------------------------
__global__ void attn_combine(const float* __restrict__ part,
                             float* __restrict__ attn,
                             const float* __restrict__ alphas,
                             const float* __restrict__ gattn)
{
    int i = blockIdx.x * blockDim.x + threadIdx.x;
    const int total = NN_*HEADS_*VV_*VV_;
    if (i >= total) return;
    int b  = i / (VV_*VV_);
    int uv = i - b*(VV_*VV_);
    float s = 0.f;
#pragma unroll
    for (int sk = 0; sk < SPLITK2; sk++)
        s += part[(size_t)(b*SPLITK2 + sk)*(VV_*VV_) + uv];
    attn[i] = tanhf(s * (1.f/(HCH_*TT_))) * alphas[b & (HEADS_-1)] + gattn[uv];
}

static inline int cdiv(int a, int b) { return (a + b - 1) / b; }

extern "C" void kernel_launch(void* const* d_in, const int* in_sizes, int n_in,
                              void* d_out, int out_size)
{
    const float* x_q    = (const float*)d_in[0];
    const float* x_kv   = (const float*)d_in[1];
    const float* wq     = (const float*)d_in[2];
    const float* bq     = (const float*)d_in[3];
    const float* wk     = (const float*)d_in[4];
    const float* bk     = (const float*)d_in[5];
    const float* wp     = (const float*)d_in[6];
    const float* bp     = (const float*)d_in[7];
    const float* alphas = (const float*)d_in[8];
    const float* gattn  = (const float*)d_in[9];
    float* out = (float*)d_out;

    float *q, *k, *attn, *part, *vals;
    cudaGetSymbolAddress((void**)&q,    g_q);
    cudaGetSymbolAddress((void**)&k,    g_k);
    cudaGetSymbolAddress((void**)&attn, g_attn);
    cudaGetSymbolAddress((void**)&part, g_part);
    cudaGetSymbolAddress((void**)&vals, g_vals);

    const int smemF = 2 * (128*40 + 32*132) * 4;   // 74752 B
    const int smemT = 2 * (32*132 + 32*132) * 4;   // 67584 B
    cudaFuncSetAttribute(mma_gemm<1,false>, cudaFuncAttributeMaxDynamicSharedMemorySize, smemF);
    cudaFuncSetAttribute(mma_gemm<0,false>, cudaFuncAttributeMaxDynamicSharedMemorySize, smemF);
    cudaFuncSetAttribute(mma_gemm<3,true >, cudaFuncAttributeMaxDynamicSharedMemorySize, smemT);

    dim3 blk(512);

    // 1) q = wq @ x_q + bq ; k = wk @ x_kv + bk   (per n: 192 x 12000, K=192)
    {
        dim3 grid(cdiv(TV_, 128), cdiv(CC_, 128), NN_);
        mma_gemm<1,false><<<grid, blk, smemF>>>(
            wq, x_q, q, CC_, TV_, CC_, CC_, TV_, TV_,
            0, 0, (long)CC_*TV_, 0, (long)CC_*TV_, 0,
            1, 1, CC_, bq);
        mma_gemm<1,false><<<grid, blk, smemF>>>(
            wk, x_kv, k, CC_, TV_, CC_, CC_, TV_, TV_,
            0, 0, (long)CC_*TV_, 0, (long)CC_*TV_, 0,
            1, 1, CC_, bk);
    }

    // 2) scores: per (n,s): 100 x 100, K = 5760, split-K = 5, raw partials
    {
        dim3 grid(1, 1, NN_*HEADS_*SPLITK2);
        mma_gemm<3,true><<<grid, blk, smemT>>>(
            q, k, part, VV_, VV_, HCH_*TT_, VV_, VV_, VV_,
            (long)CC_*TV_, (long)HCH_*TV_,
            (long)CC_*TV_, (long)HCH_*TV_,
            0, 0,
            HEADS_, SPLITK2, KCHUNK2, nullptr);
        attn_combine<<<cdiv(NN_*HEADS_*VV_*VV_, 256), 256>>>(part, attn, alphas, gattn);
    }

    // 3) vals[n,s] = x_kv[n] @ attn[n,s]   (per (n,s): 23040 x 100, K=100)
    {
        dim3 grid(1, cdiv(CC_*TT_, 128), NN_*HEADS_);
        mma_gemm<0,false><<<grid, blk, smemF>>>(
            x_kv, attn, vals, CC_*TT_, VV_, VV_, VV_, VV_, VV_,
            (long)CC_*TV_, 0,
            (long)HEADS_*VV_*VV_, (long)VV_*VV_,
            (long)HEADS_*CC_*TV_, (long)CC_*TV_,
            HEADS_, 1, VV_, nullptr);
    }

    // 4) out[n] = wp @ vals[n] + bp   (per n: 192 x 12000, K=768)
    {
        dim3 grid(cdiv(TV_, 128), cdiv(CC_, 128), NN_);
        mma_gemm<1,false><<<grid, blk, smemF>>>(
            wp, vals, out, CC_, TV_, HEADS_*CC_, HEADS_*CC_, TV_, TV_,
            0, 0, (long)HEADS_*CC_*TV_, 0, (long)CC_*TV_, 0,
            1, 1, HEADS_*CC_, bp);
    }
}

// round 6
// speedup vs baseline: 1.0019x; 1.0019x over previous
#include <cuda_runtime.h>
#include <math.h>
#include <stdint.h>

// Problem constants
#define NN_    16
#define CC_    192
#define TT_    120
#define VV_    100
#define HEADS_ 4
#define HCH_   48
#define TV_    (TT_*VV_)      // 12000

#define SPLITK2 5
#define KCHUNK2 1152          // 5760 / 5, multiple of 32

// Scratch (device globals: allocation-free rule)
__device__ float g_q[NN_*CC_*TV_];                        // 147.5 MB
__device__ float g_k[NN_*CC_*TV_];                        // 147.5 MB
__device__ float g_attn[NN_*HEADS_*VV_*VV_];              // 2.56 MB
__device__ float g_part[NN_*HEADS_*SPLITK2*VV_*VV_];      // 12.8 MB
__device__ float g_vals[NN_*HEADS_*CC_*TV_];              // 590 MB

// ---------------------------------------------------------------------------
// helpers
// ---------------------------------------------------------------------------
__device__ __forceinline__ void cp16(float* s, const float* g, bool ok) {
    uint32_t sa = (uint32_t)__cvta_generic_to_shared(s);
    int sz = ok ? 16 : 0;
    asm volatile("cp.async.cg.shared.global [%0], [%1], 16, %2;\n"
                 :: "r"(sa), "l"(g), "r"(sz));
}

// Split v0,v1 (k and k+1) into packed bf16 hi and lo fragments.
// reg layout: low 16 bits = element k (v0), high 16 bits = element k+1 (v1).
__device__ __forceinline__ void cvt_hilo(float v0, float v1, uint32_t& h, uint32_t& l) {
    asm("cvt.rn.bf16x2.f32 %0, %1, %2;" : "=r"(h) : "f"(v1), "f"(v0));
    float h0 = __uint_as_float(h << 16);
    float h1 = __uint_as_float(h & 0xffff0000u);
    asm("cvt.rn.bf16x2.f32 %0, %1, %2;" : "=r"(l) : "f"(v1 - h1), "f"(v0 - h0));
}

__device__ __forceinline__ void mma_bf16(float* c, const uint32_t* a, const uint32_t* b) {
    asm volatile(
        "mma.sync.aligned.m16n8k16.row.col.f32.bf16.bf16.f32 "
        "{%0,%1,%2,%3}, {%4,%5,%6,%7}, {%8,%9}, {%0,%1,%2,%3};\n"
        : "+f"(c[0]), "+f"(c[1]), "+f"(c[2]), "+f"(c[3])
        : "r"(a[0]), "r"(a[1]), "r"(a[2]), "r"(a[3]), "r"(b[0]), "r"(b[1]));
}

// ---------------------------------------------------------------------------
// bf16x3 emulated-fp32 GEMM.
//   C[m,n] = sum_k A(m,k) * B(k,n)
//   AKM=false : A[m*lda + k]   (row k-contiguous)
//   AKM=true  : A[k*lda + m]   (k-major, used by the attention-score GEMM)
//   B always B[k*ldb + n]
// Tiles: 128x128x32, 512 threads = 16 warps (4x4), warp tile 32x32.
// EPI: 0 = plain store, 1 = +bias[m], 3 = raw partial store (split-K)
// ---------------------------------------------------------------------------
template<int EPI, bool AKM>
__global__ __launch_bounds__(512)
void mma_gemm(const float* __restrict__ A, const float* __restrict__ B,
              float* __restrict__ C,
              int M, int N, int K, int lda, int ldb, int ldc,
              long aO, long aI, long bO, long bI, long cO, long cI,
              int innerCnt, int splitK, int kChunk,
              const float* __restrict__ bias)
{
    extern __shared__ float smem[];
    constexpr int AROW = 40;                 // padded row (32 k + 8 pad) for AKM=false
    constexpr int KROW = 132;                // padded row (128 + 4) for k-major tiles
    constexpr int ASZ  = AKM ? 32*KROW : 128*AROW;
    constexpr int BSZ  = 32*KROW;
    constexpr int STG  = ASZ + BSZ;

    const int bz    = blockIdx.z;
    const int b     = bz / splitK;
    const int sk    = bz - b*splitK;
    const int outer = b / innerCnt;
    const int inner = b - outer*innerCnt;
    A += outer*aO + inner*aI;
    B += outer*bO + inner*bI;
    if (EPI == 3) C += (size_t)bz * ((size_t)M * (size_t)N);
    else          C += outer*cO + inner*cI;

    const int kbeg = sk * kChunk;
    const int kend = min(K, kbeg + kChunk);

    const int tid    = threadIdx.x;
    const int wid    = tid >> 5;
    const int lane   = tid & 31;
    const int grp    = lane >> 2;    // 0..7
    const int thr    = lane & 3;     // 0..3
    const int warpM  = (wid >> 2) * 32;
    const int warpN  = (wid & 3) * 32;
    const int blockM = blockIdx.y * 128;
    const int blockN = blockIdx.x * 128;

    float acc[2][4][4];
#pragma unroll
    for (int i = 0; i < 2; i++)
#pragma unroll
        for (int j = 0; j < 4; j++)
#pragma unroll
            for (int l = 0; l < 4; l++) acc[i][j][l] = 0.f;

    // ---- async copy of one k-chunk into stage ----
    auto copy_chunk = [&](int k0, int stage) {
        float* As = smem + stage*STG;
        float* Bs = As + ASZ;
        if (AKM) {
#pragma unroll
            for (int e = 0; e < 2; e++) {
                int kr = (tid >> 5) + e*16;
                int g  = tid & 31;
                bool ok = (k0 + kr < kend) && (blockM + g*4 < M);
                cp16(As + kr*KROW + g*4,
                     A + (size_t)(k0 + kr)*lda + blockM + g*4, ok);
            }
        } else {
#pragma unroll
            for (int e = 0; e < 2; e++) {
                int m = (tid >> 3) + e*64;
                int g = tid & 7;
                bool ok = (blockM + m < M) && (k0 + g*4 < kend);
                cp16(As + m*AROW + g*4,
                     A + (size_t)(blockM + m)*lda + k0 + g*4, ok);
            }
        }
#pragma unroll
        for (int e = 0; e < 2; e++) {
            int kr = (tid >> 5) + e*16;
            int g  = tid & 31;
            bool ok = (k0 + kr < kend) && (blockN + g*4 < N);
            cp16(Bs + kr*KROW + g*4,
                 B + (size_t)(k0 + kr)*ldb + blockN + g*4, ok);
        }
        asm volatile("cp.async.commit_group;\n" ::: "memory");
    };

    // ---- compute one k-chunk (two k16 steps), 3 MMAs per tile (bf16x3) ----
    auto compute_chunk = [&](int stage) {
        const float* As = smem + stage*STG;
        const float* Bs = As + ASZ;
#pragma unroll
        for (int ks = 0; ks < 2; ks++) {
            const int kof = ks * 16;
            uint32_t ah[2][4], al[2][4], bh[4][2], bl[4][2];
#pragma unroll
            for (int mt = 0; mt < 2; mt++) {
                const int m0 = warpM + mt*16 + grp;
                if (!AKM) {
                    float2 v00 = *(const float2*)(As + (size_t)m0*AROW     + kof + thr*2);
                    float2 v10 = *(const float2*)(As + (size_t)(m0+8)*AROW + kof + thr*2);
                    float2 v01 = *(const float2*)(As + (size_t)m0*AROW     + kof + thr*2 + 8);
                    float2 v11 = *(const float2*)(As + (size_t)(m0+8)*AROW + kof + thr*2 + 8);
                    cvt_hilo(v00.x, v00.y, ah[mt][0], al[mt][0]);
                    cvt_hilo(v10.x, v10.y, ah[mt][1], al[mt][1]);
                    cvt_hilo(v01.x, v01.y, ah[mt][2], al[mt][2]);
                    cvt_hilo(v11.x, v11.y, ah[mt][3], al[mt][3]);
                } else {
                    const int k0 = kof + thr*2;
                    cvt_hilo(As[(k0  )*KROW + m0  ], As[(k0+1)*KROW + m0  ], ah[mt][0], al[mt][0]);
                    cvt_hilo(As[(k0  )*KROW + m0+8], As[(k0+1)*KROW + m0+8], ah[mt][1], al[mt][1]);
                    cvt_hilo(As[(k0+8)*KROW + m0  ], As[(k0+9)*KROW + m0  ], ah[mt][2], al[mt][2]);
                    cvt_hilo(As[(k0+8)*KROW + m0+8], As[(k0+9)*KROW + m0+8], ah[mt][3], al[mt][3]);
                }
            }
#pragma unroll
            for (int nt = 0; nt < 4; nt++) {
                const int n0 = warpN + nt*8 + grp;
                const int k0 = kof + thr*2;
                cvt_hilo(Bs[(k0  )*KROW + n0], Bs[(k0+1)*KROW + n0], bh[nt][0], bl[nt][0]);
                cvt_hilo(Bs[(k0+8)*KROW + n0], Bs[(k0+9)*KROW + n0], bh[nt][1], bl[nt][1]);
            }
#pragma unroll
            for (int mt = 0; mt < 2; mt++)
#pragma unroll
                for (int nt = 0; nt < 4; nt++) {
                    mma_bf16(acc[mt][nt], ah[mt], bh[nt]);
                    mma_bf16(acc[mt][nt], al[mt], bh[nt]);
                    mma_bf16(acc[mt][nt], ah[mt], bl[nt]);
                }
        }
    };

    const int nk = (kend - kbeg + 31) / 32;
    copy_chunk(kbeg, 0);
    for (int kt = 0; kt < nk; kt++) {
        if (kt + 1 < nk) {
            copy_chunk(kbeg + (kt+1)*32, (kt+1) & 1);
            asm volatile("cp.async.wait_group 1;\n" ::: "memory");
        } else {
            asm volatile("cp.async.wait_group 0;\n" ::: "memory");
        }
        __syncthreads();
        compute_chunk(kt & 1);
        __syncthreads();
    }

    // ---- epilogue ----
#pragma unroll
    for (int mt = 0; mt < 2; mt++) {
        const int mrow0 = blockM + warpM + mt*16 + grp;
#pragma unroll
        for (int half = 0; half < 2; half++) {
            const int m = mrow0 + half*8;
            if (m >= M) continue;
            float badd = 0.f;
            if (EPI == 1) badd = bias[m];
#pragma unroll
            for (int nt = 0; nt < 4; nt++) {
                const int n = blockN + warpN + nt*8 + thr*2;
                if (n >= N) continue;
                float v0 = acc[mt][nt][half*2 + 0] + badd;
                float v1 = acc[mt][nt][half*2 + 1] + badd;
                *(float2*)(C + (size_t)m*ldc + n) = make_float2(v0, v1);
            }
        }
    }
}

// ---------------------------------------------------------------------------
// split-K combine + attention epilogue: tanh(sum/5760)*alpha + global_attn
// ---------------------------------------------------------------------------
__global__ void attn_combine(const float* __restrict__ part,
                             float* __restrict__ attn,
                             const float* __restrict__ alphas,
                             const float* __restrict__ gattn)
{
    int i = blockIdx.x * blockDim.x + threadIdx.x;
    const int total = NN_*HEADS_*VV_*VV_;
    if (i >= total) return;
    int b  = i / (VV_*VV_);
    int uv = i - b*(VV_*VV_);
    float s = 0.f;
#pragma unroll
    for (int sk = 0; sk < SPLITK2; sk++)
        s += part[(size_t)(b*SPLITK2 + sk)*(VV_*VV_) + uv];
    attn[i] = tanhf(s * (1.f/(HCH_*TT_))) * alphas[b & (HEADS_-1)] + gattn[uv];
}

static inline int cdiv(int a, int b) { return (a + b - 1) / b; }

extern "C" void kernel_launch(void* const* d_in, const int* in_sizes, int n_in,
                              void* d_out, int out_size)
{
    const float* x_q    = (const float*)d_in[0];
    const float* x_kv   = (const float*)d_in[1];
    const float* wq     = (const float*)d_in[2];
    const float* bq     = (const float*)d_in[3];
    const float* wk     = (const float*)d_in[4];
    const float* bk     = (const float*)d_in[5];
    const float* wp     = (const float*)d_in[6];
    const float* bp     = (const float*)d_in[7];
    const float* alphas = (const float*)d_in[8];
    const float* gattn  = (const float*)d_in[9];
    float* out = (float*)d_out;

    float *q, *k, *attn, *part, *vals;
    cudaGetSymbolAddress((void**)&q,    g_q);
    cudaGetSymbolAddress((void**)&k,    g_k);
    cudaGetSymbolAddress((void**)&attn, g_attn);
    cudaGetSymbolAddress((void**)&part, g_part);
    cudaGetSymbolAddress((void**)&vals, g_vals);

    const int smemF = 2 * (128*40 + 32*132) * 4;   // 74752 B
    const int smemT = 2 * (32*132 + 32*132) * 4;   // 67584 B
    cudaFuncSetAttribute(mma_gemm<1,false>, cudaFuncAttributeMaxDynamicSharedMemorySize, smemF);
    cudaFuncSetAttribute(mma_gemm<0,false>, cudaFuncAttributeMaxDynamicSharedMemorySize, smemF);
    cudaFuncSetAttribute(mma_gemm<3,true >, cudaFuncAttributeMaxDynamicSharedMemorySize, smemT);

    dim3 blk(512);

    // 1) q = wq @ x_q + bq ; k = wk @ x_kv + bk   (per n: 192 x 12000, K=192)
    {
        dim3 grid(cdiv(TV_, 128), cdiv(CC_, 128), NN_);
        mma_gemm<1,false><<<grid, blk, smemF>>>(
            wq, x_q, q, CC_, TV_, CC_, CC_, TV_, TV_,
            0, 0, (long)CC_*TV_, 0, (long)CC_*TV_, 0,
            1, 1, CC_, bq);
        mma_gemm<1,false><<<grid, blk, smemF>>>(
            wk, x_kv, k, CC_, TV_, CC_, CC_, TV_, TV_,
            0, 0, (long)CC_*TV_, 0, (long)CC_*TV_, 0,
            1, 1, CC_, bk);
    }

    // 2) scores: per (n,s): 100 x 100, K = 5760, split-K = 5, raw partials
    {
        dim3 grid(1, 1, NN_*HEADS_*SPLITK2);
        mma_gemm<3,true><<<grid, blk, smemT>>>(
            q, k, part, VV_, VV_, HCH_*TT_, VV_, VV_, VV_,
            (long)CC_*TV_, (long)HCH_*TV_,
            (long)CC_*TV_, (long)HCH_*TV_,
            0, 0,
            HEADS_, SPLITK2, KCHUNK2, nullptr);
        attn_combine<<<cdiv(NN_*HEADS_*VV_*VV_, 256), 256>>>(part, attn, alphas, gattn);
    }

    // 3) vals[n,s] = x_kv[n] @ attn[n,s]   (per (n,s): 23040 x 100, K=100)
    {
        dim3 grid(1, cdiv(CC_*TT_, 128), NN_*HEADS_);
        mma_gemm<0,false><<<grid, blk, smemF>>>(
            x_kv, attn, vals, CC_*TT_, VV_, VV_, VV_, VV_, VV_,
            (long)CC_*TV_, 0,
            (long)HEADS_*VV_*VV_, (long)VV_*VV_,
            (long)HEADS_*CC_*TV_, (long)CC_*TV_,
            HEADS_, 1, VV_, nullptr);
    }

    // 4) out[n] = wp @ vals[n] + bp   (per n: 192 x 12000, K=768)
    {
        dim3 grid(cdiv(TV_, 128), cdiv(CC_, 128), NN_);
        mma_gemm<1,false><<<grid, blk, smemF>>>(
            wp, vals, out, CC_, TV_, HEADS_*CC_, HEADS_*CC_, TV_, TV_,
            0, 0, (long)HEADS_*CC_*TV_, 0, (long)CC_*TV_, 0,
            1, 1, HEADS_*CC_, bp);
    }
}

// round 7
// speedup vs baseline: 1.0021x; 1.0002x over previous
#include <cuda_runtime.h>
#include <math.h>
#include <stdint.h>

// Problem constants
#define NN_    16
#define CC_    192
#define TT_    120
#define VV_    100
#define HEADS_ 4
#define HCH_   48
#define TV_    (TT_*VV_)      // 12000

#define SPLITK2 5
#define KCHUNK2 1152          // 5760 / 5, multiple of 32

// Scratch (device globals: allocation-free rule)
__device__ float g_q[NN_*CC_*TV_];                        // 147.5 MB
__device__ float g_k[NN_*CC_*TV_];                        // 147.5 MB
__device__ float g_attn[NN_*HEADS_*VV_*VV_];              // 2.56 MB
__device__ float g_part[NN_*HEADS_*SPLITK2*VV_*VV_];      // 12.8 MB
__device__ float g_vals[NN_*HEADS_*CC_*TV_];              // 590 MB

// ---------------------------------------------------------------------------
// helpers
// ---------------------------------------------------------------------------
__device__ __forceinline__ void cp16(float* s, const float* g, bool ok) {
    uint32_t sa = (uint32_t)__cvta_generic_to_shared(s);
    int sz = ok ? 16 : 0;
    asm volatile("cp.async.cg.shared.global [%0], [%1], 16, %2;\n"
                 :: "r"(sa), "l"(g), "r"(sz));
}

// Split v0,v1 (k and k+1) into packed bf16 hi and lo fragments.
// reg layout: low 16 bits = element k (v0), high 16 bits = element k+1 (v1).
__device__ __forceinline__ void cvt_hilo(float v0, float v1, uint32_t& h, uint32_t& l) {
    asm("cvt.rn.bf16x2.f32 %0, %1, %2;" : "=r"(h) : "f"(v1), "f"(v0));
    float h0 = __uint_as_float(h << 16);
    float h1 = __uint_as_float(h & 0xffff0000u);
    asm("cvt.rn.bf16x2.f32 %0, %1, %2;" : "=r"(l) : "f"(v1 - h1), "f"(v0 - h0));
}

__device__ __forceinline__ void mma_bf16(float* c, const uint32_t* a, const uint32_t* b) {
    asm volatile(
        "mma.sync.aligned.m16n8k16.row.col.f32.bf16.bf16.f32 "
        "{%0,%1,%2,%3}, {%4,%5,%6,%7}, {%8,%9}, {%0,%1,%2,%3};\n"
        : "+f"(c[0]), "+f"(c[1]), "+f"(c[2]), "+f"(c[3])
        : "r"(a[0]), "r"(a[1]), "r"(a[2]), "r"(a[3]), "r"(b[0]), "r"(b[1]));
}

// ---------------------------------------------------------------------------
// bf16x3 emulated-fp32 GEMM.
//   C[m,n] = sum_k A(m,k) * B(k,n)
//   AKM=false : A[m*lda + k]   (row k-contiguous)
//   AKM=true  : A[k*lda + m]   (k-major, used by the attention-score GEMM)
//   B always B[k*ldb + n]
// Tiles: 128x128x32, 512 threads = 16 warps (4x4), warp tile 32x32.
// EPI: 0 = plain store, 1 = +bias[m], 3 = raw partial store (split-K)
// ---------------------------------------------------------------------------
template<int EPI, bool AKM>
__global__ __launch_bounds__(512)
void mma_gemm(const float* __restrict__ A, const float* __restrict__ B,
              float* __restrict__ C,
              int M, int N, int K, int lda, int ldb, int ldc,
              long aO, long aI, long bO, long bI, long cO, long cI,
              int innerCnt, int splitK, int kChunk,
              const float* __restrict__ bias)
{
    extern __shared__ float smem[];
    constexpr int AROW = 40;                 // padded row (32 k + 8 pad) for AKM=false
    constexpr int KROW = 132;                // padded row (128 + 4) for k-major tiles
    constexpr int ASZ  = AKM ? 32*KROW : 128*AROW;
    constexpr int BSZ  = 32*KROW;
    constexpr int STG  = ASZ + BSZ;

    const int bz    = blockIdx.z;
    const int b     = bz / splitK;
    const int sk    = bz - b*splitK;
    const int outer = b / innerCnt;
    const int inner = b - outer*innerCnt;
    A += outer*aO + inner*aI;
    B += outer*bO + inner*bI;
    if (EPI == 3) C += (size_t)bz * ((size_t)M * (size_t)N);
    else          C += outer*cO + inner*cI;

    const int kbeg = sk * kChunk;
    const int kend = min(K, kbeg + kChunk);

    const int tid    = threadIdx.x;
    const int wid    = tid >> 5;
    const int lane   = tid & 31;
    const int grp    = lane >> 2;    // 0..7
    const int thr    = lane & 3;     // 0..3
    const int warpM  = (wid >> 2) * 32;
    const int warpN  = (wid & 3) * 32;
    const int blockM = blockIdx.y * 128;
    const int blockN = blockIdx.x * 128;

    float acc[2][4][4];
#pragma unroll
    for (int i = 0; i < 2; i++)
#pragma unroll
        for (int j = 0; j < 4; j++)
#pragma unroll
            for (int l = 0; l < 4; l++) acc[i][j][l] = 0.f;

    // ---- async copy of one k-chunk into stage ----
    auto copy_chunk = [&](int k0, int stage) {
        float* As = smem + stage*STG;
        float* Bs = As + ASZ;
        if (AKM) {
#pragma unroll
            for (int e = 0; e < 2; e++) {
                int kr = (tid >> 5) + e*16;
                int g  = tid & 31;
                bool ok = (k0 + kr < kend) && (blockM + g*4 < M);
                cp16(As + kr*KROW + g*4,
                     A + (size_t)(k0 + kr)*lda + blockM + g*4, ok);
            }
        } else {
#pragma unroll
            for (int e = 0; e < 2; e++) {
                int m = (tid >> 3) + e*64;
                int g = tid & 7;
                bool ok = (blockM + m < M) && (k0 + g*4 < kend);
                cp16(As + m*AROW + g*4,
                     A + (size_t)(blockM + m)*lda + k0 + g*4, ok);
            }
        }
#pragma unroll
        for (int e = 0; e < 2; e++) {
            int kr = (tid >> 5) + e*16;
            int g  = tid & 31;
            bool ok = (k0 + kr < kend) && (blockN + g*4 < N);
            cp16(Bs + kr*KROW + g*4,
                 B + (size_t)(k0 + kr)*ldb + blockN + g*4, ok);
        }
        asm volatile("cp.async.commit_group;\n" ::: "memory");
    };

    // ---- compute one k-chunk (two k16 steps), 3 MMAs per tile (bf16x3) ----
    auto compute_chunk = [&](int stage) {
        const float* As = smem + stage*STG;
        const float* Bs = As + ASZ;
#pragma unroll
        for (int ks = 0; ks < 2; ks++) {
            const int kof = ks * 16;
            uint32_t ah[2][4], al[2][4], bh[4][2], bl[4][2];
#pragma unroll
            for (int mt = 0; mt < 2; mt++) {
                const int m0 = warpM + mt*16 + grp;
                if (!AKM) {
                    float2 v00 = *(const float2*)(As + (size_t)m0*AROW     + kof + thr*2);
                    float2 v10 = *(const float2*)(As + (size_t)(m0+8)*AROW + kof + thr*2);
                    float2 v01 = *(const float2*)(As + (size_t)m0*AROW     + kof + thr*2 + 8);
                    float2 v11 = *(const float2*)(As + (size_t)(m0+8)*AROW + kof + thr*2 + 8);
                    cvt_hilo(v00.x, v00.y, ah[mt][0], al[mt][0]);
                    cvt_hilo(v10.x, v10.y, ah[mt][1], al[mt][1]);
                    cvt_hilo(v01.x, v01.y, ah[mt][2], al[mt][2]);
                    cvt_hilo(v11.x, v11.y, ah[mt][3], al[mt][3]);
                } else {
                    const int k0 = kof + thr*2;
                    cvt_hilo(As[(k0  )*KROW + m0  ], As[(k0+1)*KROW + m0  ], ah[mt][0], al[mt][0]);
                    cvt_hilo(As[(k0  )*KROW + m0+8], As[(k0+1)*KROW + m0+8], ah[mt][1], al[mt][1]);
                    cvt_hilo(As[(k0+8)*KROW + m0  ], As[(k0+9)*KROW + m0  ], ah[mt][2], al[mt][2]);
                    cvt_hilo(As[(k0+8)*KROW + m0+8], As[(k0+9)*KROW + m0+8], ah[mt][3], al[mt][3]);
                }
            }
#pragma unroll
            for (int nt = 0; nt < 4; nt++) {
                const int n0 = warpN + nt*8 + grp;
                const int k0 = kof + thr*2;
                cvt_hilo(Bs[(k0  )*KROW + n0], Bs[(k0+1)*KROW + n0], bh[nt][0], bl[nt][0]);
                cvt_hilo(Bs[(k0+8)*KROW + n0], Bs[(k0+9)*KROW + n0], bh[nt][1], bl[nt][1]);
            }
#pragma unroll
            for (int mt = 0; mt < 2; mt++)
#pragma unroll
                for (int nt = 0; nt < 4; nt++) {
                    mma_bf16(acc[mt][nt], ah[mt], bh[nt]);
                    mma_bf16(acc[mt][nt], al[mt], bh[nt]);
                    mma_bf16(acc[mt][nt], ah[mt], bl[nt]);
                }
        }
    };

    const int nk = (kend - kbeg + 31) / 32;
    copy_chunk(kbeg, 0);
    for (int kt = 0; kt < nk; kt++) {
        if (kt + 1 < nk) {
            copy_chunk(kbeg + (kt+1)*32, (kt+1) & 1);
            asm volatile("cp.async.wait_group 1;\n" ::: "memory");
        } else {
            asm volatile("cp.async.wait_group 0;\n" ::: "memory");
        }
        __syncthreads();
        compute_chunk(kt & 1);
        __syncthreads();
    }

    // ---- epilogue ----
#pragma unroll
    for (int mt = 0; mt < 2; mt++) {
        const int mrow0 = blockM + warpM + mt*16 + grp;
#pragma unroll
        for (int half = 0; half < 2; half++) {
            const int m = mrow0 + half*8;
            if (m >= M) continue;
            float badd = 0.f;
            if (EPI == 1) badd = bias[m];
#pragma unroll
            for (int nt = 0; nt < 4; nt++) {
                const int n = blockN + warpN + nt*8 + thr*2;
                if (n >= N) continue;
                float v0 = acc[mt][nt][half*2 + 0] + badd;
                float v1 = acc[mt][nt][half*2 + 1] + badd;
                *(float2*)(C + (size_t)m*ldc + n) = make_float2(v0, v1);
            }
        }
    }
}

// ---------------------------------------------------------------------------
// split-K combine + attention epilogue: tanh(sum/5760)*alpha + global_attn
// ---------------------------------------------------------------------------
__global__ void attn_combine(const float* __restrict__ part,
                             float* __restrict__ attn,
                             const float* __restrict__ alphas,
                             const float* __restrict__ gattn)
{
    int i = blockIdx.x * blockDim.x + threadIdx.x;
    const int total = NN_*HEADS_*VV_*VV_;
    if (i >= total) return;
    int b  = i / (VV_*VV_);
    int uv = i - b*(VV_*VV_);
    float s = 0.f;
#pragma unroll
    for (int sk = 0; sk < SPLITK2; sk++)
        s += part[(size_t)(b*SPLITK2 + sk)*(VV_*VV_) + uv];
    attn[i] = tanhf(s * (1.f/(HCH_*TT_))) * alphas[b & (HEADS_-1)] + gattn[uv];
}

static inline int cdiv(int a, int b) { return (a + b - 1) / b; }

extern "C" void kernel_launch(void* const* d_in, const int* in_sizes, int n_in,
                              void* d_out, int out_size)
{
    const float* x_q    = (const float*)d_in[0];
    const float* x_kv   = (const float*)d_in[1];
    const float* wq     = (const float*)d_in[2];
    const float* bq     = (const float*)d_in[3];
    const float* wk     = (const float*)d_in[4];
    const float* bk     = (const float*)d_in[5];
    const float* wp     = (const float*)d_in[6];
    const float* bp     = (const float*)d_in[7];
    const float* alphas = (const float*)d_in[8];
    const float* gattn  = (const float*)d_in[9];
    float* out = (float*)d_out;

    float *q, *k, *attn, *part, *vals;
    cudaGetSymbolAddress((void**)&q,    g_q);
    cudaGetSymbolAddress((void**)&k,    g_k);
    cudaGetSymbolAddress((void**)&attn, g_attn);
    cudaGetSymbolAddress((void**)&part, g_part);
    cudaGetSymbolAddress((void**)&vals, g_vals);

    const int smemF = 2 * (128*40 + 32*132) * 4;   // 74752 B
    const int smemT = 2 * (32*132 + 32*132) * 4;   // 67584 B
    cudaFuncSetAttribute(mma_gemm<1,false>, cudaFuncAttributeMaxDynamicSharedMemorySize, smemF);
    cudaFuncSetAttribute(mma_gemm<0,false>, cudaFuncAttributeMaxDynamicSharedMemorySize, smemF);
    cudaFuncSetAttribute(mma_gemm<3,true >, cudaFuncAttributeMaxDynamicSharedMemorySize, smemT);

    dim3 blk(512);

    // 1) q = wq @ x_q + bq ; k = wk @ x_kv + bk   (per n: 192 x 12000, K=192)
    {
        dim3 grid(cdiv(TV_, 128), cdiv(CC_, 128), NN_);
        mma_gemm<1,false><<<grid, blk, smemF>>>(
            wq, x_q, q, CC_, TV_, CC_, CC_, TV_, TV_,
            0, 0, (long)CC_*TV_, 0, (long)CC_*TV_, 0,
            1, 1, CC_, bq);
        mma_gemm<1,false><<<grid, blk, smemF>>>(
            wk, x_kv, k, CC_, TV_, CC_, CC_, TV_, TV_,
            0, 0, (long)CC_*TV_, 0, (long)CC_*TV_, 0,
            1, 1, CC_, bk);
    }

    // 2) scores: per (n,s): 100 x 100, K = 5760, split-K = 5, raw partials
    {
        dim3 grid(1, 1, NN_*HEADS_*SPLITK2);
        mma_gemm<3,true><<<grid, blk, smemT>>>(
            q, k, part, VV_, VV_, HCH_*TT_, VV_, VV_, VV_,
            (long)CC_*TV_, (long)HCH_*TV_,
            (long)CC_*TV_, (long)HCH_*TV_,
            0, 0,
            HEADS_, SPLITK2, KCHUNK2, nullptr);
        attn_combine<<<cdiv(NN_*HEADS_*VV_*VV_, 256), 256>>>(part, attn, alphas, gattn);
    }

    // 3) vals[n,s] = x_kv[n] @ attn[n,s]   (per (n,s): 23040 x 100, K=100)
    {
        dim3 grid(1, cdiv(CC_*TT_, 128), NN_*HEADS_);
        mma_gemm<0,false><<<grid, blk, smemF>>>(
            x_kv, attn, vals, CC_*TT_, VV_, VV_, VV_, VV_, VV_,
            (long)CC_*TV_, 0,
            (long)HEADS_*VV_*VV_, (long)VV_*VV_,
            (long)HEADS_*CC_*TV_, (long)CC_*TV_,
            HEADS_, 1, VV_, nullptr);
    }

    // 4) out[n] = wp @ vals[n] + bp   (per n: 192 x 12000, K=768)
    {
        dim3 grid(cdiv(TV_, 128), cdiv(CC_, 128), NN_);
        mma_gemm<1,false><<<grid, blk, smemF>>>(
            wp, vals, out, CC_, TV_, HEADS_*CC_, HEADS_*CC_, TV_, TV_,
            0, 0, (long)HEADS_*CC_*TV_, 0, (long)CC_*TV_, 0,
            1, 1, HEADS_*CC_, bp);
    }
}